// round 15
// baseline (speedup 1.0000x reference)
#include <cuda_runtime.h>
#include <cuda_fp16.h>
#include <math.h>
#include <stdint.h>

#define BS     16
#define SLEN   2048
#define DIM    1024
#define M_TOT  (BS * SLEN)   // 32768
#define NSPLIT 8
#define NSCH   64            // attn s-chunks (32 rows each)
#define QKS    8             // qenergy k-splits
#define NCHUNK 4             // states-convert chunks (pipelined with GEMM)
#define ST_BLK 4096          // convert blocks per chunk (2 rows each)

// ---------------------------------------------------------------------------
// Scratch (__device__ globals; allocation-free rule)
// ---------------------------------------------------------------------------
__device__ __align__(16) __half g_st_h[(size_t)M_TOT * DIM];    // 64MB
__device__ __align__(16) __half g_wkT_h[(size_t)DIM * DIM];     // 2MB WkT[n][k]
__device__ float g_ek_part[NSPLIT * M_TOT];
__device__ float g_q_part[QKS * BS * DIM];                      // 512KB
__device__ __align__(16) float g_attn_part[NSCH * BS * DIM];    // 4MB

__device__ __forceinline__ uint32_t smem_u32(const void* p) {
    uint32_t a;
    asm("{ .reg .u64 t; cvta.to.shared.u64 t, %1; cvt.u32.u64 %0, t; }"
        : "=r"(a) : "l"(p));
    return a;
}
__device__ __forceinline__ float tanh_fast(float x) {
    float y;
    asm("tanh.approx.f32 %0, %1;" : "=f"(y) : "f"(x));
    return y;
}

#define LDMX4(r0, r1, r2, r3, addr)                                          \
    asm volatile("ldmatrix.sync.aligned.m8n8.x4.shared.b16 {%0,%1,%2,%3}, [%4];" \
        : "=r"(r0), "=r"(r1), "=r"(r2), "=r"(r3) : "r"(addr))

#define MMAF16(c, a, b0, b1)                                                 \
    asm volatile("mma.sync.aligned.m16n8k16.row.col.f32.f16.f16.f32 "        \
        "{%0,%1,%2,%3}, {%4,%5,%6,%7}, {%8,%9}, {%0,%1,%2,%3};"              \
        : "+f"((c)[0]), "+f"((c)[1]), "+f"((c)[2]), "+f"((c)[3])             \
        : "r"((a)[0]), "r"((a)[1]), "r"((a)[2]), "r"((a)[3]),                \
          "r"(b0), "r"(b1))

#define CPASYNC16(dst, src)                                                  \
    asm volatile("cp.async.cg.shared.global [%0], [%1], 16;"                 \
                 :: "r"(dst), "l"(src))
#define CP_COMMIT()  asm volatile("cp.async.commit_group;" ::: "memory")
#define CP_WAIT0()   asm volatile("cp.async.wait_group 0;" ::: "memory")

// ---------------------------------------------------------------------------
// Prologue chunk. misc=1 (chunk 0): QE splits + WkT + states blocks.
// Other chunks: states blocks only, offset st_base.
// ---------------------------------------------------------------------------
#define NB_QE   (BS * 4 * QKS)   // 512
#define NB_WKT  1024

__global__ void __launch_bounds__(256) k_prologue(
        const float* __restrict__ states, const float* __restrict__ Wk,
        const float* __restrict__ query,  const float* __restrict__ Wq,
        int st_base, int misc) {
    __shared__ float sh[1056];
    int bx = blockIdx.x;
    const int tid = threadIdx.x;

    if (misc) {
        if (bx < NB_QE) {
            // qenergy split-K partial: raw dot product over 128 v-rows
            const int b  = bx >> 5;
            const int q  = (bx >> 3) & 3;
            const int ks = bx & 7;
            const int col = q * 256 + tid;
            const int v0 = ks * 128;
            float* qs = sh;
            if (tid < 128) qs[tid] = query[b * DIM + v0 + tid];
            __syncthreads();
            float a0 = 0.f, a1 = 0.f, a2 = 0.f, a3 = 0.f;
            const float* wp = Wq + (size_t)v0 * DIM + col;
            #pragma unroll 8
            for (int v = 0; v < 128; v += 4) {
                a0 = fmaf(qs[v],     wp[(size_t)v * DIM],       a0);
                a1 = fmaf(qs[v + 1], wp[(size_t)(v + 1) * DIM], a1);
                a2 = fmaf(qs[v + 2], wp[(size_t)(v + 2) * DIM], a2);
                a3 = fmaf(qs[v + 3], wp[(size_t)(v + 3) * DIM], a3);
            }
            g_q_part[(ks * BS + b) * DIM + col] = (a0 + a1) + (a2 + a3);
            return;
        }
        if (bx < NB_QE + NB_WKT) {
            // WkT[d][v] = Wk[v][d] -> fp16
            float (*tile)[33] = (float(*)[33])sh;
            const int t = bx - NB_QE;
            const int d0 = (t & 31) * 32, v0 = (t >> 5) * 32;
            const int tx = tid & 31, ty = tid >> 5;   // (32, 8)
            #pragma unroll
            for (int j = 0; j < 4; j++)
                tile[ty + j * 8][tx] =
                    Wk[(size_t)(v0 + ty + j * 8) * DIM + d0 + tx];
            __syncthreads();
            #pragma unroll
            for (int j = 0; j < 4; j++) {
                const int dy = ty + j * 8;
                g_wkT_h[(size_t)(d0 + dy) * DIM + v0 + tx] =
                    __float2half_rn(tile[tx][dy]);
            }
            return;
        }
        bx -= NB_QE + NB_WKT;
    }
    // states -> fp16 (2 x float4 per thread)
    const size_t base = ((size_t)(st_base + bx) * 512 + tid * 2) * 4;
    #pragma unroll
    for (int r = 0; r < 2; r++) {
        const size_t i = base + r * 4;
        const float4 v = *(const float4*)(states + i);
        __half2 p01, p23;
        p01.x = __float2half_rn(v.x); p01.y = __float2half_rn(v.y);
        p23.x = __float2half_rn(v.z); p23.y = __float2half_rn(v.w);
        uint2 hp;
        hp.x = *(const uint32_t*)&p01; hp.y = *(const uint32_t*)&p23;
        *(uint2*)(g_st_h + i) = hp;
    }
}

// ---------------------------------------------------------------------------
// GEMM: single-pass fp16, CTA 128x128, 8 warps of 64(M)x32(N) tiles,
// K in 16 slabs of 64, cp.async double-buffered, 2 CTAs/SM.
// Launched in 4 m-quarters (m_off), pipelined with convert chunks.
// Fused tanh*We epilogue. smem row pitch 144B: conflict-free ldmatrix.
// ---------------------------------------------------------------------------
#define PITCH    144
#define TILE_B   (128 * PITCH)         // 18432
#define OFF_A    0
#define OFF_B    TILE_B
#define BUF_SZ   (2 * TILE_B)          // 36864
#define RED_OFF  (2 * BUF_SZ)          // 73728
#define GEMM_SMEM (RED_OFF + 4 * 128 * 4)   // 75776

__device__ __forceinline__ void issue_slab(
        uint32_t sb, const __half* __restrict__ A,
        const __half* __restrict__ B, int k0, int tid) {
    #pragma unroll
    for (int p = 0; p < 4; p++) {
        const int idx = p * 256 + tid;      // 1024 chunks of 16B per tile
        const int row = idx >> 3, seg = idx & 7;
        const uint32_t d = (uint32_t)(row * PITCH + seg * 16);
        const size_t g = (size_t)row * DIM + k0 + seg * 8;
        CPASYNC16(sb + OFF_A + d, A + g);
        CPASYNC16(sb + OFF_B + d, B + g);
    }
}

__global__ void __launch_bounds__(256, 2) k_gemm_mma(
        const float* __restrict__ bk, const float* __restrict__ We_k,
        int m_off) {
    extern __shared__ char smem[];
    const uint32_t sbase = smem_u32(smem);
    const int tid = threadIdx.x;
    const int wid = tid >> 5;
    const int lid = tid & 31;
    const int n_blk = blockIdx.x;           // 0..7
    const int m_blk = m_off + blockIdx.y;   // quarter offset

    const int wm = wid >> 2, wn = wid & 3;      // 2 x 4 warp grid
    const int m0 = wm * 64, n0 = wn * 32;

    const int a_r  = (lid & 7) + ((lid >> 3) & 1) * 8;
    const int a_cs = (lid >> 4) * 16;
    const int b_r  = (lid & 7) + (lid >> 4) * 8;
    const int b_ks = ((lid >> 3) & 1) * 16;

    const __half* A = g_st_h + (size_t)m_blk * 128 * DIM;
    const __half* B = g_wkT_h + (size_t)n_blk * 128 * DIM;

    float acc[4][4][4];
    #pragma unroll
    for (int i = 0; i < 4; i++)
        #pragma unroll
        for (int j = 0; j < 4; j++)
            #pragma unroll
            for (int c = 0; c < 4; c++) acc[i][j][c] = 0.f;

    issue_slab(sbase, A, B, 0, tid);
    CP_COMMIT();

    for (int s = 0; s < 16; s++) {
        CP_WAIT0();
        __syncthreads();
        if (s < 15) {
            issue_slab(sbase + (uint32_t)((s + 1) & 1) * BUF_SZ, A, B,
                       (s + 1) * 64, tid);
            CP_COMMIT();
        }
        const uint32_t ab = sbase + (uint32_t)(s & 1) * BUF_SZ;

        #pragma unroll
        for (int kk = 0; kk < 4; kk++) {
            const int kb = kk * 32;
            uint32_t ah[4][4], bf[4][2];
            #pragma unroll
            for (int fm = 0; fm < 4; fm++)
                LDMX4(ah[fm][0], ah[fm][1], ah[fm][2], ah[fm][3],
                      ab + OFF_A + (uint32_t)((m0 + fm * 16 + a_r) * PITCH + kb + a_cs));
            #pragma unroll
            for (int q = 0; q < 2; q++)
                LDMX4(bf[2 * q][0], bf[2 * q][1], bf[2 * q + 1][0], bf[2 * q + 1][1],
                      ab + OFF_B + (uint32_t)((n0 + q * 16 + b_r) * PITCH + kb + b_ks));
            #pragma unroll
            for (int fm = 0; fm < 4; fm++)
                #pragma unroll
                for (int fn = 0; fn < 4; fn++)
                    MMAF16(acc[fm][fn], ah[fm], bf[fn][0], bf[fn][1]);
        }
    }

    // Fused epilogue: tanh(relu(k + bk)) * We reduced over this 128-N tile
    float bkv[4][2], wev[4][2];
    #pragma unroll
    for (int fn = 0; fn < 4; fn++)
        #pragma unroll
        for (int j = 0; j < 2; j++) {
            const int n = n_blk * 128 + n0 + fn * 8 + (lid & 3) * 2 + j;
            bkv[fn][j] = bk[n];
            wev[fn][j] = We_k[n];
        }

    float* sred = (float*)(smem + RED_OFF);
    #pragma unroll
    for (int fm = 0; fm < 4; fm++)
        #pragma unroll
        for (int ch = 0; ch < 2; ch++) {
            float p = 0.f;
            #pragma unroll
            for (int fn = 0; fn < 4; fn++)
                #pragma unroll
                for (int j = 0; j < 2; j++) {
                    float v = acc[fm][fn][ch * 2 + j] + bkv[fn][j];
                    v = fmaxf(v, 0.f);
                    p = fmaf(tanh_fast(v), wev[fn][j], p);
                }
            p += __shfl_down_sync(0xffffffffu, p, 1, 4);
            p += __shfl_down_sync(0xffffffffu, p, 2, 4);
            if ((lid & 3) == 0)
                sred[wn * 128 + m0 + fm * 16 + ch * 8 + (lid >> 2)] = p;
        }
    __syncthreads();
    if (tid < 128) {
        const float e = sred[tid] + sred[128 + tid] + sred[256 + tid] + sred[384 + tid];
        g_ek_part[n_blk * M_TOT + m_blk * 128 + tid] = e;
    }
}

// ---------------------------------------------------------------------------
// softmax over s (512 threads; head: finish eq from q_part splits)
// ---------------------------------------------------------------------------
__global__ void __launch_bounds__(512) k_softmax(
        const float* __restrict__ bq, const float* __restrict__ We,
        const float* __restrict__ be, float* __restrict__ out_w) {
    const int b = blockIdx.x;
    const int tid = threadIdx.x;
    __shared__ float red[512];

    float eqp = 0.f;
    #pragma unroll
    for (int i = 0; i < 2; i++) {
        const int col = tid + 512 * i;
        float v = 0.f;
        #pragma unroll
        for (int ks = 0; ks < QKS; ks++)
            v += g_q_part[(ks * BS + b) * DIM + col];
        v = fmaxf(v + bq[col], 0.f);
        eqp = fmaf(tanh_fast(v), We[col], eqp);
    }
    red[tid] = eqp; __syncthreads();
    for (int s = 256; s > 0; s >>= 1) {
        if (tid < s) red[tid] += red[tid + s];
        __syncthreads();
    }
    const float base = red[0] + be[0];
    __syncthreads();

    float e[4];
    float lmax = -1e30f;
    #pragma unroll
    for (int r = 0; r < 4; r++) {
        const int s = r * 512 + tid;
        float v = base;
        #pragma unroll
        for (int p = 0; p < NSPLIT; p++)
            v += g_ek_part[p * M_TOT + b * SLEN + s];
        e[r] = v;
        lmax = fmaxf(lmax, v);
    }
    red[tid] = lmax; __syncthreads();
    for (int s = 256; s > 0; s >>= 1) {
        if (tid < s) red[tid] = fmaxf(red[tid], red[tid + s]);
        __syncthreads();
    }
    const float gmax = red[0];
    __syncthreads();
    float lsum = 0.f;
    #pragma unroll
    for (int r = 0; r < 4; r++) {
        e[r] = expf(e[r] - gmax);
        lsum += e[r];
    }
    red[tid] = lsum; __syncthreads();
    for (int s = 256; s > 0; s >>= 1) {
        if (tid < s) red[tid] += red[tid + s];
        __syncthreads();
    }
    const float inv = 1.f / red[0];
    #pragma unroll
    for (int r = 0; r < 4; r++)
        out_w[b * SLEN + r * 512 + tid] = e[r] * inv;
}

// ---------------------------------------------------------------------------
// attn partials: w staged in smem, 32 fully-unrolled independent row loads
// ---------------------------------------------------------------------------
__global__ void __launch_bounds__(256) k_attn_part(const float* __restrict__ w) {
    const int sc = blockIdx.x;   // 0..63
    const int b  = blockIdx.y;   // 0..15
    const int tid = threadIdx.x;
    __shared__ float ws[32];
    if (tid < 32) ws[tid] = w[b * SLEN + sc * 32 + tid];
    __syncthreads();

    float4 acc = make_float4(0.f, 0.f, 0.f, 0.f);
    const __half* base = g_st_h + ((size_t)b * SLEN + sc * 32) * DIM + tid * 4;
    #pragma unroll
    for (int sl = 0; sl < 32; sl++) {
        const float wv = ws[sl];
        const uint2 p = *(const uint2*)(base + (size_t)sl * DIM);
        const __half2 h01 = *(const __half2*)&p.x;
        const __half2 h23 = *(const __half2*)&p.y;
        const float2 f01 = __half22float2(h01);
        const float2 f23 = __half22float2(h23);
        acc.x = fmaf(wv, f01.x, acc.x);
        acc.y = fmaf(wv, f01.y, acc.y);
        acc.z = fmaf(wv, f23.x, acc.z);
        acc.w = fmaf(wv, f23.y, acc.w);
    }
    *(float4*)(g_attn_part + ((size_t)(sc * BS + b)) * DIM + tid * 4) = acc;
}

__global__ void __launch_bounds__(256) k_attn_reduce(float* __restrict__ out_attn) {
    const int idx = blockIdx.x * 256 + threadIdx.x;
    const int b = idx >> 10;
    const int d = idx & 1023;
    float s = 0.f;
    #pragma unroll
    for (int p = 0; p < NSCH; p++)
        s += g_attn_part[(size_t)(p * BS + b) * DIM + d];
    out_attn[idx] = s;
}

// ---------------------------------------------------------------------------
extern "C" void kernel_launch(void* const* d_in, const int* in_sizes, int n_in,
                              void* d_out, int out_size) {
    const float* query  = (const float*)d_in[0];
    const float* states = (const float*)d_in[1];
    const float* Wq     = (const float*)d_in[2];
    const float* bq     = (const float*)d_in[3];
    const float* Wk     = (const float*)d_in[4];
    const float* bk     = (const float*)d_in[5];
    const float* We     = (const float*)d_in[6];
    const float* be     = (const float*)d_in[7];

    float* out      = (float*)d_out;
    float* out_w    = out;                 // attn_weights (16, 2048)
    float* out_attn = out + BS * SLEN;     // attn         (16, 1024)

    // One-time resources (host-side objects only; no device memory).
    static cudaStream_t s1 = nullptr;
    static cudaEvent_t evc[NCHUNK], evj;
    if (s1 == nullptr) {
        cudaStreamCreateWithFlags(&s1, cudaStreamNonBlocking);
        for (int k = 0; k < NCHUNK; k++)
            cudaEventCreateWithFlags(&evc[k], cudaEventDisableTiming);
        cudaEventCreateWithFlags(&evj, cudaEventDisableTiming);
        cudaFuncSetAttribute(k_gemm_mma,
                             cudaFuncAttributeMaxDynamicSharedMemorySize,
                             GEMM_SMEM);
    }

    // Pipelined prologue (stream 0) / GEMM quarters (stream s1)
    k_prologue<<<NB_QE + NB_WKT + ST_BLK, 256>>>(states, Wk, query, Wq, 0, 1);
    cudaEventRecord(evc[0], 0);
    for (int k = 1; k < NCHUNK; k++) {
        k_prologue<<<ST_BLK, 256>>>(states, Wk, query, Wq, k * ST_BLK, 0);
        cudaEventRecord(evc[k], 0);
    }
    for (int k = 0; k < NCHUNK; k++) {
        cudaStreamWaitEvent(s1, evc[k], 0);
        k_gemm_mma<<<dim3(NSPLIT, 64), 256, GEMM_SMEM, s1>>>(bk, We + DIM,
                                                             k * 64);
    }
    cudaEventRecord(evj, s1);
    cudaStreamWaitEvent(0, evj, 0);

    k_softmax<<<BS, 512>>>(bq, We, be, out_w);
    k_attn_part<<<dim3(NSCH, BS), 256>>>(out_w);
    k_attn_reduce<<<BS * DIM / 256, 256>>>(out_attn);
}

// round 16
// speedup vs baseline: 1.1177x; 1.1177x over previous
#include <cuda_runtime.h>
#include <cuda_fp16.h>
#include <math.h>
#include <stdint.h>

#define BS     16
#define SLEN   2048
#define DIM    1024
#define M_TOT  (BS * SLEN)   // 32768
#define NSPLIT 8
#define NSCH   64            // attn s-chunks (32 rows each)
#define QKS    8             // qenergy k-splits

// ---------------------------------------------------------------------------
// Scratch (__device__ globals; allocation-free rule)
// ---------------------------------------------------------------------------
__device__ __align__(16) __half g_st_h[(size_t)M_TOT * DIM];    // 64MB
__device__ __align__(16) __half g_wkT_h[(size_t)DIM * DIM];     // 2MB WkT[n][k]
__device__ float g_ek_part[NSPLIT * M_TOT];
__device__ float g_q_part[QKS * BS * DIM];                      // 512KB
__device__ __align__(16) float g_attn_part[NSCH * BS * DIM];    // 4MB

__device__ __forceinline__ uint32_t smem_u32(const void* p) {
    uint32_t a;
    asm("{ .reg .u64 t; cvta.to.shared.u64 t, %1; cvt.u32.u64 %0, t; }"
        : "=r"(a) : "l"(p));
    return a;
}
__device__ __forceinline__ float tanh_fast(float x) {
    float y;
    asm("tanh.approx.f32 %0, %1;" : "=f"(y) : "f"(x));
    return y;
}

#define LDMX4(r0, r1, r2, r3, addr)                                          \
    asm volatile("ldmatrix.sync.aligned.m8n8.x4.shared.b16 {%0,%1,%2,%3}, [%4];" \
        : "=r"(r0), "=r"(r1), "=r"(r2), "=r"(r3) : "r"(addr))

#define MMAF16(c, a, b0, b1)                                                 \
    asm volatile("mma.sync.aligned.m16n8k16.row.col.f32.f16.f16.f32 "        \
        "{%0,%1,%2,%3}, {%4,%5,%6,%7}, {%8,%9}, {%0,%1,%2,%3};"              \
        : "+f"((c)[0]), "+f"((c)[1]), "+f"((c)[2]), "+f"((c)[3])             \
        : "r"((a)[0]), "r"((a)[1]), "r"((a)[2]), "r"((a)[3]),                \
          "r"(b0), "r"(b1))

#define CPASYNC16(dst, src)                                                  \
    asm volatile("cp.async.cg.shared.global [%0], [%1], 16;"                 \
                 :: "r"(dst), "l"(src))
#define CP_COMMIT()  asm volatile("cp.async.commit_group;" ::: "memory")
#define CP_WAIT0()   asm volatile("cp.async.wait_group 0;" ::: "memory")

// ---------------------------------------------------------------------------
// Merged prologue. Block order: qenergy splits FIRST, then WkT, then states.
// States convert: 4 independent float4 loads per thread (MLP=4).
// ---------------------------------------------------------------------------
#define NB_QE   (BS * 4 * QKS)   // 512
#define NB_WKT  1024
#define NB_ST   8192             // 4 rows per block

__global__ void __launch_bounds__(256) k_prologue(
        const float* __restrict__ states, const float* __restrict__ Wk,
        const float* __restrict__ query,  const float* __restrict__ Wq) {
    __shared__ float sh[1056];
    const int bx = blockIdx.x;
    const int tid = threadIdx.x;

    if (bx < NB_QE) {
        // qenergy split-K partial: raw dot product over 128 v-rows
        const int b  = bx >> 5;
        const int q  = (bx >> 3) & 3;
        const int ks = bx & 7;
        const int col = q * 256 + tid;
        const int v0 = ks * 128;
        float* qs = sh;
        if (tid < 128) qs[tid] = query[b * DIM + v0 + tid];
        __syncthreads();
        float a0 = 0.f, a1 = 0.f, a2 = 0.f, a3 = 0.f;
        const float* wp = Wq + (size_t)v0 * DIM + col;
        #pragma unroll 8
        for (int v = 0; v < 128; v += 4) {
            a0 = fmaf(qs[v],     wp[(size_t)v * DIM],       a0);
            a1 = fmaf(qs[v + 1], wp[(size_t)(v + 1) * DIM], a1);
            a2 = fmaf(qs[v + 2], wp[(size_t)(v + 2) * DIM], a2);
            a3 = fmaf(qs[v + 3], wp[(size_t)(v + 3) * DIM], a3);
        }
        g_q_part[(ks * BS + b) * DIM + col] = (a0 + a1) + (a2 + a3);
    } else if (bx < NB_QE + NB_WKT) {
        // WkT[d][v] = Wk[v][d] -> fp16
        float (*tile)[33] = (float(*)[33])sh;
        const int t = bx - NB_QE;
        const int d0 = (t & 31) * 32, v0 = (t >> 5) * 32;
        const int tx = tid & 31, ty = tid >> 5;   // (32, 8)
        #pragma unroll
        for (int j = 0; j < 4; j++)
            tile[ty + j * 8][tx] = Wk[(size_t)(v0 + ty + j * 8) * DIM + d0 + tx];
        __syncthreads();
        #pragma unroll
        for (int j = 0; j < 4; j++) {
            const int dy = ty + j * 8;
            g_wkT_h[(size_t)(d0 + dy) * DIM + v0 + tx] =
                __float2half_rn(tile[tx][dy]);
        }
    } else {
        // states -> fp16: 4 independent float4 loads per thread, unrolled
        const size_t base = ((size_t)(bx - NB_QE - NB_WKT) * 1024 + tid) * 4;
        float4 v[4];
        #pragma unroll
        for (int r = 0; r < 4; r++)
            v[r] = *(const float4*)(states + base + (size_t)r * 1024);
        #pragma unroll
        for (int r = 0; r < 4; r++) {
            __half2 p01, p23;
            p01.x = __float2half_rn(v[r].x); p01.y = __float2half_rn(v[r].y);
            p23.x = __float2half_rn(v[r].z); p23.y = __float2half_rn(v[r].w);
            uint2 hp;
            hp.x = *(const uint32_t*)&p01; hp.y = *(const uint32_t*)&p23;
            *(uint2*)(g_st_h + base + (size_t)r * 1024) = hp;
        }
    }
}

// ---------------------------------------------------------------------------
// GEMM: single-pass fp16, CTA 128x128, 8 warps of 64(M)x32(N) tiles,
// K in 16 slabs of 64, cp.async double-buffered, 2 CTAs/SM.
// (R10/R12/R14 configuration — measured optimum at legacy-mma sequencer floor.)
// Fused tanh*We epilogue. smem row pitch 144B: conflict-free ldmatrix.
// ---------------------------------------------------------------------------
#define PITCH    144
#define TILE_B   (128 * PITCH)         // 18432
#define OFF_A    0
#define OFF_B    TILE_B
#define BUF_SZ   (2 * TILE_B)          // 36864
#define RED_OFF  (2 * BUF_SZ)          // 73728
#define GEMM_SMEM (RED_OFF + 4 * 128 * 4)   // 75776

__device__ __forceinline__ void issue_slab(
        uint32_t sb, const __half* __restrict__ A,
        const __half* __restrict__ B, int k0, int tid) {
    #pragma unroll
    for (int p = 0; p < 4; p++) {
        const int idx = p * 256 + tid;      // 1024 chunks of 16B per tile
        const int row = idx >> 3, seg = idx & 7;
        const uint32_t d = (uint32_t)(row * PITCH + seg * 16);
        const size_t g = (size_t)row * DIM + k0 + seg * 8;
        CPASYNC16(sb + OFF_A + d, A + g);
        CPASYNC16(sb + OFF_B + d, B + g);
    }
}

__global__ void __launch_bounds__(256, 2) k_gemm_mma(
        const float* __restrict__ bk, const float* __restrict__ We_k) {
    extern __shared__ char smem[];
    const uint32_t sbase = smem_u32(smem);
    const int tid = threadIdx.x;
    const int wid = tid >> 5;
    const int lid = tid & 31;
    const int n_blk = blockIdx.x;   // 0..7
    const int m_blk = blockIdx.y;   // 0..255

    const int wm = wid >> 2, wn = wid & 3;      // 2 x 4 warp grid
    const int m0 = wm * 64, n0 = wn * 32;

    const int a_r  = (lid & 7) + ((lid >> 3) & 1) * 8;
    const int a_cs = (lid >> 4) * 16;
    const int b_r  = (lid & 7) + (lid >> 4) * 8;
    const int b_ks = ((lid >> 3) & 1) * 16;

    const __half* A = g_st_h + (size_t)m_blk * 128 * DIM;
    const __half* B = g_wkT_h + (size_t)n_blk * 128 * DIM;

    float acc[4][4][4];
    #pragma unroll
    for (int i = 0; i < 4; i++)
        #pragma unroll
        for (int j = 0; j < 4; j++)
            #pragma unroll
            for (int c = 0; c < 4; c++) acc[i][j][c] = 0.f;

    issue_slab(sbase, A, B, 0, tid);
    CP_COMMIT();

    for (int s = 0; s < 16; s++) {
        CP_WAIT0();
        __syncthreads();
        if (s < 15) {
            issue_slab(sbase + (uint32_t)((s + 1) & 1) * BUF_SZ, A, B,
                       (s + 1) * 64, tid);
            CP_COMMIT();
        }
        const uint32_t ab = sbase + (uint32_t)(s & 1) * BUF_SZ;

        #pragma unroll
        for (int kk = 0; kk < 4; kk++) {
            const int kb = kk * 32;
            uint32_t ah[4][4], bf[4][2];
            #pragma unroll
            for (int fm = 0; fm < 4; fm++)
                LDMX4(ah[fm][0], ah[fm][1], ah[fm][2], ah[fm][3],
                      ab + OFF_A + (uint32_t)((m0 + fm * 16 + a_r) * PITCH + kb + a_cs));
            #pragma unroll
            for (int q = 0; q < 2; q++)
                LDMX4(bf[2 * q][0], bf[2 * q][1], bf[2 * q + 1][0], bf[2 * q + 1][1],
                      ab + OFF_B + (uint32_t)((n0 + q * 16 + b_r) * PITCH + kb + b_ks));
            #pragma unroll
            for (int fm = 0; fm < 4; fm++)
                #pragma unroll
                for (int fn = 0; fn < 4; fn++)
                    MMAF16(acc[fm][fn], ah[fm], bf[fn][0], bf[fn][1]);
        }
    }

    // Fused epilogue: tanh(relu(k + bk)) * We reduced over this 128-N tile
    float bkv[4][2], wev[4][2];
    #pragma unroll
    for (int fn = 0; fn < 4; fn++)
        #pragma unroll
        for (int j = 0; j < 2; j++) {
            const int n = n_blk * 128 + n0 + fn * 8 + (lid & 3) * 2 + j;
            bkv[fn][j] = bk[n];
            wev[fn][j] = We_k[n];
        }

    float* sred = (float*)(smem + RED_OFF);
    #pragma unroll
    for (int fm = 0; fm < 4; fm++)
        #pragma unroll
        for (int ch = 0; ch < 2; ch++) {
            float p = 0.f;
            #pragma unroll
            for (int fn = 0; fn < 4; fn++)
                #pragma unroll
                for (int j = 0; j < 2; j++) {
                    float v = acc[fm][fn][ch * 2 + j] + bkv[fn][j];
                    v = fmaxf(v, 0.f);
                    p = fmaf(tanh_fast(v), wev[fn][j], p);
                }
            p += __shfl_down_sync(0xffffffffu, p, 1, 4);
            p += __shfl_down_sync(0xffffffffu, p, 2, 4);
            if ((lid & 3) == 0)
                sred[wn * 128 + m0 + fm * 16 + ch * 8 + (lid >> 2)] = p;
        }
    __syncthreads();
    if (tid < 128) {
        const float e = sred[tid] + sred[128 + tid] + sred[256 + tid] + sred[384 + tid];
        g_ek_part[n_blk * M_TOT + m_blk * 128 + tid] = e;
    }
}

// ---------------------------------------------------------------------------
// softmax over s (512 threads; head: finish eq from q_part splits)
// ---------------------------------------------------------------------------
__global__ void __launch_bounds__(512) k_softmax(
        const float* __restrict__ bq, const float* __restrict__ We,
        const float* __restrict__ be, float* __restrict__ out_w) {
    const int b = blockIdx.x;
    const int tid = threadIdx.x;
    __shared__ float red[512];

    float eqp = 0.f;
    #pragma unroll
    for (int i = 0; i < 2; i++) {
        const int col = tid + 512 * i;
        float v = 0.f;
        #pragma unroll
        for (int ks = 0; ks < QKS; ks++)
            v += g_q_part[(ks * BS + b) * DIM + col];
        v = fmaxf(v + bq[col], 0.f);
        eqp = fmaf(tanh_fast(v), We[col], eqp);
    }
    red[tid] = eqp; __syncthreads();
    for (int s = 256; s > 0; s >>= 1) {
        if (tid < s) red[tid] += red[tid + s];
        __syncthreads();
    }
    const float base = red[0] + be[0];
    __syncthreads();

    float e[4];
    float lmax = -1e30f;
    #pragma unroll
    for (int r = 0; r < 4; r++) {
        const int s = r * 512 + tid;
        float v = base;
        #pragma unroll
        for (int p = 0; p < NSPLIT; p++)
            v += g_ek_part[p * M_TOT + b * SLEN + s];
        e[r] = v;
        lmax = fmaxf(lmax, v);
    }
    red[tid] = lmax; __syncthreads();
    for (int s = 256; s > 0; s >>= 1) {
        if (tid < s) red[tid] = fmaxf(red[tid], red[tid + s]);
        __syncthreads();
    }
    const float gmax = red[0];
    __syncthreads();
    float lsum = 0.f;
    #pragma unroll
    for (int r = 0; r < 4; r++) {
        e[r] = expf(e[r] - gmax);
        lsum += e[r];
    }
    red[tid] = lsum; __syncthreads();
    for (int s = 256; s > 0; s >>= 1) {
        if (tid < s) red[tid] += red[tid + s];
        __syncthreads();
    }
    const float inv = 1.f / red[0];
    #pragma unroll
    for (int r = 0; r < 4; r++)
        out_w[b * SLEN + r * 512 + tid] = e[r] * inv;
}

// ---------------------------------------------------------------------------
// attn partials: w staged in smem, 32 fully-unrolled independent row loads
// ---------------------------------------------------------------------------
__global__ void __launch_bounds__(256) k_attn_part(const float* __restrict__ w) {
    const int sc = blockIdx.x;   // 0..63
    const int b  = blockIdx.y;   // 0..15
    const int tid = threadIdx.x;
    __shared__ float ws[32];
    if (tid < 32) ws[tid] = w[b * SLEN + sc * 32 + tid];
    __syncthreads();

    float4 acc = make_float4(0.f, 0.f, 0.f, 0.f);
    const __half* base = g_st_h + ((size_t)b * SLEN + sc * 32) * DIM + tid * 4;
    #pragma unroll
    for (int sl = 0; sl < 32; sl++) {
        const float wv = ws[sl];
        const uint2 p = *(const uint2*)(base + (size_t)sl * DIM);
        const __half2 h01 = *(const __half2*)&p.x;
        const __half2 h23 = *(const __half2*)&p.y;
        const float2 f01 = __half22float2(h01);
        const float2 f23 = __half22float2(h23);
        acc.x = fmaf(wv, f01.x, acc.x);
        acc.y = fmaf(wv, f01.y, acc.y);
        acc.z = fmaf(wv, f23.x, acc.z);
        acc.w = fmaf(wv, f23.y, acc.w);
    }
    *(float4*)(g_attn_part + ((size_t)(sc * BS + b)) * DIM + tid * 4) = acc;
}

__global__ void __launch_bounds__(256) k_attn_reduce(float* __restrict__ out_attn) {
    const int idx = blockIdx.x * 256 + threadIdx.x;
    const int b = idx >> 10;
    const int d = idx & 1023;
    float s = 0.f;
    #pragma unroll
    for (int p = 0; p < NSCH; p++)
        s += g_attn_part[(size_t)(p * BS + b) * DIM + d];
    out_attn[idx] = s;
}

// ---------------------------------------------------------------------------
extern "C" void kernel_launch(void* const* d_in, const int* in_sizes, int n_in,
                              void* d_out, int out_size) {
    const float* query  = (const float*)d_in[0];
    const float* states = (const float*)d_in[1];
    const float* Wq     = (const float*)d_in[2];
    const float* bq     = (const float*)d_in[3];
    const float* Wk     = (const float*)d_in[4];
    const float* bk     = (const float*)d_in[5];
    const float* We     = (const float*)d_in[6];
    const float* be     = (const float*)d_in[7];

    float* out      = (float*)d_out;
    float* out_w    = out;                 // attn_weights (16, 2048)
    float* out_attn = out + BS * SLEN;     // attn         (16, 1024)

    cudaFuncSetAttribute(k_gemm_mma, cudaFuncAttributeMaxDynamicSharedMemorySize,
                         GEMM_SMEM);

    k_prologue<<<NB_QE + NB_WKT + NB_ST, 256>>>(states, Wk, query, Wq);
    k_gemm_mma<<<dim3(NSPLIT, M_TOT / 128), 256, GEMM_SMEM>>>(bk, We + DIM);
    k_softmax<<<BS, 512>>>(bq, We, be, out_w);
    k_attn_part<<<dim3(NSCH, BS), 256>>>(out_w);
    k_attn_reduce<<<BS * DIM / 256, 256>>>(out_attn);
}